// round 2
// baseline (speedup 1.0000x reference)
#include <cuda_runtime.h>
#include <cuda_fp16.h>
#include <stdint.h>

// Problem dims
#define Bdim 512
#define Tdim 1024
#define Ddim 55
#define Hdim 256
#define Odim 9
#define G4H  1024          // 4*H gate columns
#define KDIM 320           // 64 (x + pad) + 256 (h)
// Tiling
#define MG   4             // M groups of 128 batch rows
#define MT   128
#define NSL  16            // N slices per group
#define NT   64            // gate cols per slice (= 16 hidden units * 4 gates)
#define NCTA (MG * NSL)    // 64
#define NTHREADS 256
// SMEM padded strides (halves / floats)
#define AP 328
#define WP 328
#define GP 68

// ---------------- persistent device scratch (allowed: static __device__) ----
__device__ __half g_xT[(size_t)Tdim * Bdim * 64];     // 64 MB  [t][b][k<64]
__device__ __half g_W[(size_t)G4H * KDIM];            // reordered [n][k], fp16
__device__ float  g_bias[G4H];
__device__ float  g_corr0[(size_t)Bdim * G4H];        // step-0 correction
__device__ __half g_h16[2][Bdim * Hdim];              // double-buffered h (fp16)
__device__ float  g_h32[2][Bdim * Hdim];              // double-buffered h (fp32)
__device__ int    g_cnt[MG];                          // per-group arrival counters

// ---------------- helpers ----------------
__device__ __forceinline__ float sigf(float x) {
    return __fdividef(1.0f, 1.0f + __expf(-x));
}
__device__ __forceinline__ float tanh_fast(float x) {
    return __fdividef(2.0f, 1.0f + __expf(-2.0f * x)) - 1.0f;
}
__device__ __forceinline__ void cp_async16(uint32_t smem_addr, const void* gptr) {
    asm volatile("cp.async.cg.shared.global [%0], [%1], 16;\n"
                 :: "r"(smem_addr), "l"(gptr) : "memory");
}

// Column reordering: reordered n -> original gate index
// slice s = n/64, c = n%64, gate = c/16, unit = 16*s + c%16, orig = gate*256 + unit
__device__ __forceinline__ int orig_gate_col(int n) {
    int s = n >> 6, c = n & 63;
    return (c >> 4) * 256 + (s << 4) + (c & 15);
}

// ---------------- prep kernels (rerun every replay; they reset all state) ----
__global__ void prep_weights(const float* __restrict__ W_ih, const float* __restrict__ b_ih,
                             const float* __restrict__ W_hh, const float* __restrict__ b_hh,
                             const float* __restrict__ W_ho, const float* __restrict__ b_ho) {
    int n = blockIdx.x;         // 0..1023
    int k = threadIdx.x;        // 0..319
    int g = orig_gate_col(n);
    float w;
    if (k < Ddim) {
        w = W_ih[g * 64 + k];
    } else if (k < 64) {
        w = 0.0f;
    } else {
        int kh = k - 64;
        w = W_hh[g * Hdim + kh];
        #pragma unroll
        for (int j = 0; j < Odim; j++)
            w += W_ho[j * Hdim + kh] * W_ih[g * 64 + Ddim + j];
    }
    g_W[(size_t)n * KDIM + k] = __float2half_rn(w);
    if (k == 0) {
        float bb = b_ih[g] + b_hh[g];
        #pragma unroll
        for (int j = 0; j < Odim; j++)
            bb += b_ho[j] * W_ih[g * 64 + Ddim + j];
        g_bias[n] = bb;
    }
    if (n == 0 && k < MG) g_cnt[k] = 0;   // reset sync counters each replay
}

__global__ void prep_x(const float* __restrict__ x) {
    size_t idx = (size_t)blockIdx.x * 256 + threadIdx.x;  // t*B*64 total
    int k = (int)(idx & 63);
    size_t r = idx >> 6;
    int b = (int)(r & (Bdim - 1));
    int t = (int)(r >> 9);
    float v = (k < Ddim) ? x[((size_t)b * Tdim + t) * Ddim + k] : 0.0f;
    g_xT[idx] = __float2half_rn(v);
}

__global__ void prep_state(const float* __restrict__ h0,
                           const float* __restrict__ W_ih,
                           const float* __restrict__ W_ho,
                           const float* __restrict__ b_ho) {
    int b = blockIdx.x;
    int tid = threadIdx.x;
    // init h buffers (parity 0 = h_{-1} = h0)
    float hv = h0[b * Hdim + tid];
    g_h16[0][b * Hdim + tid] = __float2half_rn(hv);
    g_h32[0][b * Hdim + tid] = hv;
    // step-0 correction: -(h0@W_ho^T + b_ho)@Wip^T
    __shared__ float tmp[Odim];
    if (tid < Odim) {
        float a = b_ho[tid];
        for (int k = 0; k < Hdim; k++)
            a += h0[b * Hdim + k] * W_ho[tid * Hdim + k];
        tmp[tid] = a;
    }
    __syncthreads();
    for (int n = tid; n < G4H; n += 256) {
        int g = orig_gate_col(n);
        float a = 0.0f;
        #pragma unroll
        for (int j = 0; j < Odim; j++)
            a += tmp[j] * W_ih[g * 64 + Ddim + j];
        g_corr0[(size_t)b * G4H + n] = -a;
    }
}

// ---------------- SMEM layout (dynamic) ----------------
#define OFF_AS   0
#define OFF_WS   (OFF_AS + MT * AP * 2)          // 83968
#define OFF_GS   (OFF_WS + NT * WP * 2)          // 125952
#define OFF_CS   (OFF_GS + MT * GP * 4)          // 160768
#define OFF_WHO  (OFF_CS + MT * 16 * 4)          // 168960
#define OFF_BIAS (OFF_WHO + Odim * Hdim * 4)     // 178176
#define OFF_BHO  (OFF_BIAS + NT * 4)             // 178432
#define SMEM_BYTES (OFF_BHO + 64)                // 178496

// out_{t_store} for this CTA's 8 designated rows, read from fp32 h buffer p.
__device__ __forceinline__ void compute_out(int t_store, int p, int mBase, int s,
                                            const float* Who_s, const float* bho_s,
                                            float* __restrict__ out) {
    int wid = threadIdx.x >> 5, lane = threadIdx.x & 31;
    int b = mBase + s * 8 + wid;                   // wid 0..7 -> 8 rows
    const float* hp = g_h32[p] + (size_t)b * Hdim;
    float a[Odim];
    #pragma unroll
    for (int j = 0; j < Odim; j++) a[j] = 0.0f;
    #pragma unroll
    for (int k8 = 0; k8 < 8; k8++) {
        float hv = __ldcg(&hp[k8 * 32 + lane]);
        #pragma unroll
        for (int j = 0; j < Odim; j++)
            a[j] += hv * Who_s[j * Hdim + k8 * 32 + lane];
    }
    #pragma unroll
    for (int off = 16; off > 0; off >>= 1) {
        #pragma unroll
        for (int j = 0; j < Odim; j++)
            a[j] += __shfl_xor_sync(0xffffffffu, a[j], off);
    }
    if (lane < Odim)
        out[((size_t)b * Tdim + t_store) * Odim + lane] = a[lane] + bho_s[lane];
}

__global__ void __launch_bounds__(NTHREADS, 1)
rnn_kernel(const float* __restrict__ c0, const float* __restrict__ W_ho,
           const float* __restrict__ b_ho, float* __restrict__ out) {
    extern __shared__ char smem[];
    __half* As    = (__half*)(smem + OFF_AS);
    __half* Ws    = (__half*)(smem + OFF_WS);
    float*  gs    = (float*)(smem + OFF_GS);
    float*  cs    = (float*)(smem + OFF_CS);
    float*  Who_s = (float*)(smem + OFF_WHO);
    float*  bias_s= (float*)(smem + OFF_BIAS);
    float*  bho_s = (float*)(smem + OFF_BHO);

    const int tid = threadIdx.x;
    const int m = blockIdx.x & (MG - 1);
    const int s = blockIdx.x >> 2;
    const int mBase = m * MT;
    const int wid = tid >> 5, lane = tid & 31;
    const int wm = wid & 3, wn = wid >> 2;          // warp tile: rows wm*32, cols wn*32
    const int qg = lane >> 2;                       // 0..7
    const int qk = (lane & 3) * 2;                  // 0,2,4,6

    const uint32_t As_base = (uint32_t)__cvta_generic_to_shared(As);

    // ---- one-time loads ----
    for (int i = tid; i < NT * 40; i += NTHREADS) { // W slice: 64 rows x 40 x 16B
        int c = i / 40, ch = i % 40;
        *(uint4*)&Ws[c * WP + ch * 8] =
            *(const uint4*)&g_W[((size_t)(s * NT + c)) * KDIM + ch * 8];
    }
    for (int i = tid; i < Odim * Hdim; i += NTHREADS) Who_s[i] = W_ho[i];
    if (tid < NT)  bias_s[tid] = g_bias[s * NT + tid];
    if (tid < Odim) bho_s[tid] = b_ho[tid];
    {   // c init: thread owns unit u = tid&15, rows rb+16i
        int u = tid & 15, rb = tid >> 4;
        #pragma unroll
        for (int i = 0; i < 8; i++) {
            int r = rb + i * 16;
            cs[r * 16 + u] = c0[(size_t)(mBase + r) * Hdim + s * 16 + u];
        }
    }
    __syncthreads();

    // ---- time loop ----
    for (int t = 0; t < Tdim; t++) {
        const int p  = t & 1;        // h_{t-1} buffer
        const int p2 = p ^ 1;        // h_t buffer

        if (t > 0) {
            if (tid == 0) {
                int tgt = t * NSL;
                while (*(volatile int*)&g_cnt[m] < tgt) { __nanosleep(40); }
                __threadfence();
            }
            __syncthreads();
        }

        // A tile load: [128 x 320] fp16: x part (8 chunks) + h part (32 chunks)
        const __half* xrow_base = g_xT + ((size_t)t * Bdim + mBase) * 64;
        const __half* hrow_base = g_h16[p] + (size_t)mBase * Hdim;
        for (int i = tid; i < MT * 40; i += NTHREADS) {
            int r = i / 40, ch = i % 40;
            uint32_t dst = As_base + (uint32_t)(r * AP + ch * 8) * 2;
            const void* src = (ch < 8)
                ? (const void*)(xrow_base + (size_t)r * 64 + ch * 8)
                : (const void*)(hrow_base + (size_t)r * Hdim + (ch - 8) * 8);
            cp_async16(dst, src);
        }
        asm volatile("cp.async.commit_group;\n" ::: "memory");

        // out_{t-1}: buffer p is stable until we arrive at end of this step
        if (t > 0) compute_out(t - 1, p, mBase, s, Who_s, bho_s, out);

        asm volatile("cp.async.wait_group 0;\n" ::: "memory");
        __syncthreads();

        // ---- MMA: [128 x 320] @ [320 x 64] -> fp32 accum ----
        float acc[2][4][4];
        #pragma unroll
        for (int a0 = 0; a0 < 2; a0++)
            #pragma unroll
            for (int b0 = 0; b0 < 4; b0++)
                #pragma unroll
                for (int c0i = 0; c0i < 4; c0i++) acc[a0][b0][c0i] = 0.0f;

        #pragma unroll 5
        for (int k0 = 0; k0 < KDIM; k0 += 16) {
            uint32_t af[2][4];
            #pragma unroll
            for (int am = 0; am < 2; am++) {
                const __half* ap = As + (wm * 32 + am * 16 + qg) * AP + k0 + qk;
                af[am][0] = *(const uint32_t*)(ap);
                af[am][1] = *(const uint32_t*)(ap + 8 * AP);
                af[am][2] = *(const uint32_t*)(ap + 8);
                af[am][3] = *(const uint32_t*)(ap + 8 * AP + 8);
            }
            #pragma unroll
            for (int bn = 0; bn < 4; bn++) {
                const __half* bp = Ws + (wn * 32 + bn * 8 + qg) * WP + k0 + qk;
                uint32_t bf0 = *(const uint32_t*)(bp);
                uint32_t bf1 = *(const uint32_t*)(bp + 8);
                #pragma unroll
                for (int am = 0; am < 2; am++) {
                    asm volatile(
                        "mma.sync.aligned.m16n8k16.row.col.f32.f16.f16.f32 "
                        "{%0,%1,%2,%3}, {%4,%5,%6,%7}, {%8,%9}, {%0,%1,%2,%3};\n"
                        : "+f"(acc[am][bn][0]), "+f"(acc[am][bn][1]),
                          "+f"(acc[am][bn][2]), "+f"(acc[am][bn][3])
                        : "r"(af[am][0]), "r"(af[am][1]), "r"(af[am][2]), "r"(af[am][3]),
                          "r"(bf0), "r"(bf1));
                }
            }
        }

        // stage gates to smem
        #pragma unroll
        for (int am = 0; am < 2; am++) {
            #pragma unroll
            for (int bn = 0; bn < 4; bn++) {
                int r = wm * 32 + am * 16 + qg;
                int c = wn * 32 + bn * 8 + (lane & 3) * 2;
                *(float2*)&gs[r * GP + c]       = make_float2(acc[am][bn][0], acc[am][bn][1]);
                *(float2*)&gs[(r + 8) * GP + c] = make_float2(acc[am][bn][2], acc[am][bn][3]);
            }
        }
        __syncthreads();

        // ---- epilogue: LSTM cell for 16 units x 128 rows ----
        {
            int u = tid & 15, rb = tid >> 4;
            int unit = s * 16 + u;
            #pragma unroll
            for (int i = 0; i < 8; i++) {
                int r = rb + i * 16;
                float ig = gs[r * GP + u]       + bias_s[u];
                float fg = gs[r * GP + 16 + u]  + bias_s[16 + u];
                float gg = gs[r * GP + 32 + u]  + bias_s[32 + u];
                float og = gs[r * GP + 48 + u]  + bias_s[48 + u];
                int b = mBase + r;
                if (t == 0) {
                    const float* cp = g_corr0 + (size_t)b * G4H + s * NT;
                    ig += cp[u]; fg += cp[16 + u]; gg += cp[32 + u]; og += cp[48 + u];
                }
                float iS = sigf(ig), fS = sigf(fg), gT = tanh_fast(gg), oS = sigf(og);
                float cN = fS * cs[r * 16 + u] + iS * gT;
                cs[r * 16 + u] = cN;
                float h = oS * tanh_fast(cN);
                g_h16[p2][b * Hdim + unit] = __float2half_rn(h);
                g_h32[p2][b * Hdim + unit] = h;
            }
        }
        __threadfence();
        __syncthreads();
        if (tid == 0) atomicAdd(&g_cnt[m], 1);
    }

    // final output out_{T-1}
    if (tid == 0) {
        while (*(volatile int*)&g_cnt[m] < Tdim * NSL) { __nanosleep(40); }
        __threadfence();
    }
    __syncthreads();
    compute_out(Tdim - 1, 0, mBase, s, Who_s, bho_s, out);
}

// ---------------- launch ----------------
extern "C" void kernel_launch(void* const* d_in, const int* in_sizes, int n_in,
                              void* d_out, int out_size) {
    const float* x    = (const float*)d_in[0];
    // d_in[1] = lengths (unused by the reference)
    const float* h0   = (const float*)d_in[2];
    const float* c0   = (const float*)d_in[3];
    const float* W_ih = (const float*)d_in[4];
    const float* b_ih = (const float*)d_in[5];
    const float* W_hh = (const float*)d_in[6];
    const float* b_hh = (const float*)d_in[7];
    const float* W_ho = (const float*)d_in[8];
    const float* b_ho = (const float*)d_in[9];
    float* out = (float*)d_out;

    cudaFuncSetAttribute(rnn_kernel, cudaFuncAttributeMaxDynamicSharedMemorySize, SMEM_BYTES);

    prep_weights<<<G4H, KDIM>>>(W_ih, b_ih, W_hh, b_hh, W_ho, b_ho);
    prep_x<<<(Tdim * Bdim * 64) / 256, 256>>>(x);
    prep_state<<<Bdim, 256>>>(h0, W_ih, W_ho, b_ho);
    rnn_kernel<<<NCTA, NTHREADS, SMEM_BYTES>>>(c0, W_ho, b_ho, out);
}

// round 5
// speedup vs baseline: 1.9758x; 1.9758x over previous
#include <cuda_runtime.h>
#include <cuda_fp16.h>
#include <stdint.h>

// Problem dims
#define Bdim 512
#define Tdim 1024
#define Ddim 55
#define Hdim 256
#define Odim 9
#define G4H  1024          // 4*H gate columns
#define KDIM 320           // 64 (x + pad) + 256 (h)
// Tiling: 16 M-groups of 32 rows x 8 N-slices of 128 gate cols = 128 CTAs
#define MG   16
#define MT   32
#define NSL  8
#define NT   128           // gate cols per slice (= 32 hidden units * 4 gates)
#define UPS  32            // units per slice
#define NCTA (MG * NSL)    // 128
#define NTHREADS 256
// SMEM padded strides (halves / floats)
#define AP 328
#define WP 328
#define GP 132

// ---------------- persistent device scratch ----------------
__device__ __half g_xT[(size_t)Tdim * Bdim * 64];     // [t][b][k<64]
__device__ __half g_W[(size_t)G4H * KDIM];            // reordered [n][k], fp16
__device__ float  g_bias[G4H];
__device__ float  g_corr0[(size_t)Bdim * G4H];        // step-0 correction
__device__ __half g_h16[2][Bdim * Hdim];              // double-buffered h (fp16)
__device__ int    g_cnt[MG * 32];                     // padded per-group counters

// ---------------- helpers ----------------
__device__ __forceinline__ float tanha(float x) {
    float y; asm("tanh.approx.f32 %0, %1;" : "=f"(y) : "f"(x)); return y;
}
__device__ __forceinline__ float sigf(float x) {
    return fmaf(tanha(0.5f * x), 0.5f, 0.5f);
}
__device__ __forceinline__ void cp_async16(uint32_t smem_addr, const void* gptr) {
    asm volatile("cp.async.cg.shared.global [%0], [%1], 16;\n"
                 :: "r"(smem_addr), "l"(gptr) : "memory");
}
__device__ __forceinline__ int ld_acquire(int* p) {
    int v; asm volatile("ld.acquire.gpu.global.s32 %0, [%1];" : "=r"(v) : "l"(p) : "memory");
    return v;
}
__device__ __forceinline__ void red_release_add(int* p, int v) {
    asm volatile("red.release.gpu.global.add.s32 [%0], %1;" :: "l"(p), "r"(v) : "memory");
}

// Column reordering: reordered n -> original gate index
// slice s = n/128, c = n%128, gate = c/32, unit = 32*s + c%32, orig = gate*256 + unit
__device__ __forceinline__ int orig_gate_col(int n) {
    int s = n >> 7, c = n & 127;
    return (c >> 5) * 256 + (s << 5) + (c & 31);
}

// ---------------- prep kernels (rerun every replay; reset all state) ----
__global__ void prep_weights(const float* __restrict__ W_ih, const float* __restrict__ b_ih,
                             const float* __restrict__ W_hh, const float* __restrict__ b_hh,
                             const float* __restrict__ W_ho, const float* __restrict__ b_ho) {
    int n = blockIdx.x;         // 0..1023
    int k = threadIdx.x;        // 0..319
    int g = orig_gate_col(n);
    float w;
    if (k < Ddim) {
        w = W_ih[g * 64 + k];
    } else if (k < 64) {
        w = 0.0f;
    } else {
        int kh = k - 64;
        w = W_hh[g * Hdim + kh];
        #pragma unroll
        for (int j = 0; j < Odim; j++)
            w += W_ho[j * Hdim + kh] * W_ih[g * 64 + Ddim + j];
    }
    g_W[(size_t)n * KDIM + k] = __float2half_rn(w);
    if (k == 0) {
        float bb = b_ih[g] + b_hh[g];
        #pragma unroll
        for (int j = 0; j < Odim; j++)
            bb += b_ho[j] * W_ih[g * 64 + Ddim + j];
        g_bias[n] = bb;
    }
    if (n == 0 && k < MG) g_cnt[k * 32] = 0;   // reset sync counters each replay
}

__global__ void prep_x(const float* __restrict__ x) {
    size_t idx = (size_t)blockIdx.x * 256 + threadIdx.x;  // t*B*64 total
    int k = (int)(idx & 63);
    size_t r = idx >> 6;
    int b = (int)(r & (Bdim - 1));
    int t = (int)(r >> 9);
    float v = (k < Ddim) ? x[((size_t)b * Tdim + t) * Ddim + k] : 0.0f;
    g_xT[idx] = __float2half_rn(v);
}

__global__ void prep_state(const float* __restrict__ h0,
                           const float* __restrict__ W_ih,
                           const float* __restrict__ W_ho,
                           const float* __restrict__ b_ho) {
    int b = blockIdx.x;
    int tid = threadIdx.x;
    g_h16[0][b * Hdim + tid] = __float2half_rn(h0[b * Hdim + tid]);
    __shared__ float tmp[Odim];
    if (tid < Odim) {
        float a = b_ho[tid];
        for (int k = 0; k < Hdim; k++)
            a += h0[b * Hdim + k] * W_ho[tid * Hdim + k];
        tmp[tid] = a;
    }
    __syncthreads();
    for (int n = tid; n < G4H; n += 256) {
        int g = orig_gate_col(n);
        float a = 0.0f;
        #pragma unroll
        for (int j = 0; j < Odim; j++)
            a += tmp[j] * W_ih[g * 64 + Ddim + j];
        g_corr0[(size_t)b * G4H + n] = -a;
    }
}

// ---------------- SMEM layout (dynamic) ----------------
#define OFF_AS   0
#define OFF_WS   (OFF_AS + MT * AP * 2)          // 20992
#define OFF_GS   (OFF_WS + NT * WP * 2)          // 104960
#define OFF_CS   (OFF_GS + MT * GP * 4)          // 121856
#define OFF_WHO  (OFF_CS + MT * UPS * 4)         // 125952
#define OFF_BIAS (OFF_WHO + Odim * Hdim * 4)     // 135168
#define OFF_BHO  (OFF_BIAS + NT * 4)             // 135680
#define SMEM_BYTES (OFF_BHO + 64)                // 135744

// out_{t_store} for this CTA's 4 designated rows (warps 0..3), fp16 h buffer p.
__device__ __forceinline__ void compute_out(int t_store, int p, int mBase, int s,
                                            const float* Who_s, const float* bho_s,
                                            float* __restrict__ out) {
    int wid = threadIdx.x >> 5, lane = threadIdx.x & 31;
    if (wid >= 4) return;
    int b = mBase + s * 4 + wid;
    const __half2* hp = (const __half2*)(g_h16[p] + (size_t)b * Hdim);
    float a[Odim];
    #pragma unroll
    for (int j = 0; j < Odim; j++) a[j] = 0.0f;
    #pragma unroll
    for (int c = 0; c < 4; c++) {
        __half2 hv2 = __ldcg(&hp[c * 32 + lane]);
        float lo = __low2float(hv2), hi = __high2float(hv2);
        int k = (c * 32 + lane) * 2;
        #pragma unroll
        for (int j = 0; j < Odim; j++) {
            a[j] = fmaf(lo, Who_s[j * Hdim + k], a[j]);
            a[j] = fmaf(hi, Who_s[j * Hdim + k + 1], a[j]);
        }
    }
    #pragma unroll
    for (int off = 16; off > 0; off >>= 1) {
        #pragma unroll
        for (int j = 0; j < Odim; j++)
            a[j] += __shfl_xor_sync(0xffffffffu, a[j], off);
    }
    if (lane < Odim)
        out[((size_t)b * Tdim + t_store) * Odim + lane] = a[lane] + bho_s[lane];
}

__global__ void __launch_bounds__(NTHREADS, 1)
rnn_kernel(const float* __restrict__ c0, const float* __restrict__ W_ho,
           const float* __restrict__ b_ho, float* __restrict__ out) {
    extern __shared__ char smem[];
    __half* As    = (__half*)(smem + OFF_AS);
    __half* Ws    = (__half*)(smem + OFF_WS);
    float*  gs    = (float*)(smem + OFF_GS);
    float*  cs    = (float*)(smem + OFF_CS);
    float*  Who_s = (float*)(smem + OFF_WHO);
    float*  bias_s= (float*)(smem + OFF_BIAS);
    float*  bho_s = (float*)(smem + OFF_BHO);

    const int tid = threadIdx.x;
    const int m = blockIdx.x & (MG - 1);       // group
    const int s = blockIdx.x >> 4;             // slice 0..7
    const int mBase = m * MT;
    const int wid = tid >> 5, lane = tid & 31;
    const int wm = wid & 1, wn = wid >> 1;     // warp tile: rows wm*16, cols wn*32
    const int qg = lane >> 2;

    const uint32_t As_base = (uint32_t)__cvta_generic_to_shared(As);
    const uint32_t Ws_base = (uint32_t)__cvta_generic_to_shared(Ws);

    // ldmatrix lane addresses
    const uint32_t a_ptr = As_base +
        (uint32_t)(((wm * 16 + (lane & 15)) * AP + ((lane >> 4) << 3)) * 2);
    const uint32_t b_ptr1 = Ws_base +
        (uint32_t)(((wn * 32 + (lane & 7) + ((lane >> 4) << 3)) * WP + (((lane >> 3) & 1) << 3)) * 2);
    const uint32_t b_ptr2 = b_ptr1 + 16 * WP * 2;

    // ---- one-time loads ----
    for (int i = tid; i < NT * 40; i += NTHREADS) { // W slice: 128 rows x 40 x 16B
        int c = i / 40, ch = i % 40;
        *(uint4*)&Ws[c * WP + ch * 8] =
            *(const uint4*)&g_W[((size_t)(s * NT + c)) * KDIM + ch * 8];
    }
    for (int i = tid; i < Odim * Hdim; i += NTHREADS) Who_s[i] = W_ho[i];
    if (tid < NT)  bias_s[tid] = g_bias[s * NT + tid];
    if (tid < Odim) bho_s[tid] = b_ho[tid];
    {   // c init: thread owns unit u = tid&31, rows rb+8i
        int u = tid & 31, rb = tid >> 5;
        #pragma unroll
        for (int i = 0; i < 4; i++) {
            int r = rb + i * 8;
            cs[r * UPS + u] = c0[(size_t)(mBase + r) * Hdim + s * UPS + u];
        }
    }
    __syncthreads();

    int* cnt = &g_cnt[m * 32];

    // ---- time loop ----
    for (int t = 0; t < Tdim; t++) {
        const int p  = t & 1;        // h_{t-1} buffer
        const int p2 = p ^ 1;        // h_t buffer

        // x-part prefetch (independent of sync): 32 rows x 8 chunks, 1/thread
        {
            const __half* xrow = g_xT + ((size_t)t * Bdim + mBase) * 64;
            int r = tid >> 3, ch = tid & 7;
            cp_async16(As_base + (uint32_t)((r * AP + ch * 8) * 2),
                       xrow + (size_t)r * 64 + ch * 8);
            asm volatile("cp.async.commit_group;\n" ::: "memory");
        }

        if (t > 0) {
            if (tid == 0) {
                int tgt = t * NSL;
                while (ld_acquire(cnt) < tgt) { __nanosleep(32); }
            }
            __syncthreads();
        }

        // h-part load: 32 rows x 32 chunks, 4/thread
        {
            const __half* hrow = g_h16[p] + (size_t)mBase * Hdim;
            #pragma unroll
            for (int it = 0; it < 4; it++) {
                int i = tid + it * NTHREADS;
                int r = i >> 5, ch = i & 31;
                cp_async16(As_base + (uint32_t)((r * AP + 64 + ch * 8) * 2),
                           hrow + (size_t)r * Hdim + ch * 8);
            }
            asm volatile("cp.async.commit_group;\n" ::: "memory");
        }

        // out_{t-1}: buffer p is stable until group advances past step t
        if (t > 0) compute_out(t - 1, p, mBase, s, Who_s, bho_s, out);

        asm volatile("cp.async.wait_group 0;\n" ::: "memory");
        __syncthreads();

        // ---- MMA: [32 x 320] @ [320 x 128] -> fp32 accum (per warp 16x32) ----
        float acc[4][4];
        #pragma unroll
        for (int b0 = 0; b0 < 4; b0++)
            #pragma unroll
            for (int c0i = 0; c0i < 4; c0i++) acc[b0][c0i] = 0.0f;

        #pragma unroll 5
        for (int k0 = 0; k0 < KDIM; k0 += 16) {
            uint32_t a0, a1, a2, a3, bb[8];
            asm volatile("ldmatrix.sync.aligned.m8n8.x4.shared.b16 {%0,%1,%2,%3}, [%4];"
                         : "=r"(a0), "=r"(a1), "=r"(a2), "=r"(a3)
                         : "r"(a_ptr + (uint32_t)(k0 * 2)));
            asm volatile("ldmatrix.sync.aligned.m8n8.x4.shared.b16 {%0,%1,%2,%3}, [%4];"
                         : "=r"(bb[0]), "=r"(bb[1]), "=r"(bb[2]), "=r"(bb[3])
                         : "r"(b_ptr1 + (uint32_t)(k0 * 2)));
            asm volatile("ldmatrix.sync.aligned.m8n8.x4.shared.b16 {%0,%1,%2,%3}, [%4];"
                         : "=r"(bb[4]), "=r"(bb[5]), "=r"(bb[6]), "=r"(bb[7])
                         : "r"(b_ptr2 + (uint32_t)(k0 * 2)));
            #pragma unroll
            for (int bn = 0; bn < 4; bn++) {
                asm volatile(
                    "mma.sync.aligned.m16n8k16.row.col.f32.f16.f16.f32 "
                    "{%0,%1,%2,%3}, {%4,%5,%6,%7}, {%8,%9}, {%0,%1,%2,%3};\n"
                    : "+f"(acc[bn][0]), "+f"(acc[bn][1]),
                      "+f"(acc[bn][2]), "+f"(acc[bn][3])
                    : "r"(a0), "r"(a1), "r"(a2), "r"(a3),
                      "r"(bb[bn * 2]), "r"(bb[bn * 2 + 1]));
            }
        }

        // stage gates to smem
        #pragma unroll
        for (int bn = 0; bn < 4; bn++) {
            int r = wm * 16 + qg;
            int c = wn * 32 + bn * 8 + (lane & 3) * 2;
            *(float2*)&gs[r * GP + c]       = make_float2(acc[bn][0], acc[bn][1]);
            *(float2*)&gs[(r + 8) * GP + c] = make_float2(acc[bn][2], acc[bn][3]);
        }
        __syncthreads();

        // ---- epilogue: LSTM cell for 32 units x 32 rows ----
        {
            int u = tid & 31, rb = tid >> 5;
            int unit = s * UPS + u;
            #pragma unroll
            for (int i = 0; i < 4; i++) {
                int r = rb + i * 8;
                float ig = gs[r * GP + u]       + bias_s[u];
                float fg = gs[r * GP + 32 + u]  + bias_s[32 + u];
                float gg = gs[r * GP + 64 + u]  + bias_s[64 + u];
                float og = gs[r * GP + 96 + u]  + bias_s[96 + u];
                int b = mBase + r;
                if (t == 0) {
                    const float* cp = g_corr0 + (size_t)b * G4H + s * NT;
                    ig += cp[u]; fg += cp[32 + u]; gg += cp[64 + u]; og += cp[96 + u];
                }
                float iS = sigf(ig), fS = sigf(fg), gT = tanha(gg), oS = sigf(og);
                float cN = fS * cs[r * UPS + u] + iS * gT;
                cs[r * UPS + u] = cN;
                float h = oS * tanha(cN);
                g_h16[p2][b * Hdim + unit] = __float2half_rn(h);
            }
        }
        __syncthreads();
        if (tid == 0) red_release_add(cnt, 1);
    }

    // final output out_{T-1} (h_{T-1} lives in buffer 0 for even Tdim)
    if (tid == 0) {
        while (ld_acquire(cnt) < Tdim * NSL) { __nanosleep(32); }
    }
    __syncthreads();
    compute_out(Tdim - 1, 0, mBase, s, Who_s, bho_s, out);
}

// ---------------- launch ----------------
extern "C" void kernel_launch(void* const* d_in, const int* in_sizes, int n_in,
                              void* d_out, int out_size) {
    const float* x    = (const float*)d_in[0];
    // d_in[1] = lengths (unused by the reference)
    const float* h0   = (const float*)d_in[2];
    const float* c0   = (const float*)d_in[3];
    const float* W_ih = (const float*)d_in[4];
    const float* b_ih = (const float*)d_in[5];
    const float* W_hh = (const float*)d_in[6];
    const float* b_hh = (const float*)d_in[7];
    const float* W_ho = (const float*)d_in[8];
    const float* b_ho = (const float*)d_in[9];
    float* out = (float*)d_out;

    cudaFuncSetAttribute(rnn_kernel, cudaFuncAttributeMaxDynamicSharedMemorySize, SMEM_BYTES);

    prep_weights<<<G4H, KDIM>>>(W_ih, b_ih, W_hh, b_hh, W_ho, b_ho);
    prep_x<<<(Tdim * Bdim * 64) / 256, 256>>>(x);
    prep_state<<<Bdim, 256>>>(h0, W_ih, W_ho, b_ho);
    rnn_kernel<<<NCTA, NTHREADS, SMEM_BYTES>>>(c0, W_ho, b_ho, out);
}

// round 6
// speedup vs baseline: 2.2054x; 1.1162x over previous
#include <cuda_runtime.h>
#include <cuda_fp16.h>
#include <stdint.h>

// Problem dims
#define Bdim 512
#define Tdim 1024
#define Ddim 55
#define Hdim 256
#define Odim 9
#define G4H  1024          // 4*H gate columns
#define KDIM 320           // 64 (x + pad) + 256 (h)
// Tiling: 16 M-groups of 32 rows x 8 N-slices of 128 gate cols = 128 CTAs
#define MG   16
#define MT   32
#define NSL  8
#define NT   128           // gate cols per slice
#define NCTA (MG * NSL)    // 128
#define NTHREADS 256
// SMEM padded strides (halves)
#define AP 328
#define WP 328

// ---------------- persistent device scratch ----------------
__device__ __half g_xT[(size_t)Tdim * Bdim * 64];     // [t][b][k<64]
__device__ __half g_W[(size_t)G4H * KDIM];            // reordered [n][k], fp16
__device__ float  g_bias[G4H];                        // reordered
__device__ float  g_corr0[(size_t)Bdim * G4H];        // step-0 correction (reordered cols)
__device__ __half g_h16[2][Bdim * Hdim];              // double-buffered h (fp16)
__device__ int    g_cnt[MG * 32];                     // padded per-group counters

// ---------------- helpers ----------------
__device__ __forceinline__ float tanha(float x) {
    float y; asm("tanh.approx.f32 %0, %1;" : "=f"(y) : "f"(x)); return y;
}
__device__ __forceinline__ float sigf(float x) {
    return fmaf(tanha(0.5f * x), 0.5f, 0.5f);
}
__device__ __forceinline__ void cp_async16(uint32_t smem_addr, const void* gptr) {
    asm volatile("cp.async.cg.shared.global [%0], [%1], 16;\n"
                 :: "r"(smem_addr), "l"(gptr) : "memory");
}
__device__ __forceinline__ int ld_acquire(int* p) {
    int v; asm volatile("ld.acquire.gpu.global.s32 %0, [%1];" : "=r"(v) : "l"(p) : "memory");
    return v;
}
__device__ __forceinline__ void red_release_add(int* p, int v) {
    asm volatile("red.release.gpu.global.add.s32 [%0], %1;" :: "l"(p), "r"(v) : "memory");
}

// Gate-interleaved column reordering: reordered n -> original gate index.
//   n = s*128 + wn*32 + gate*8 + w   (s: slice 0..7, wn: warp-tile 0..3, w: unit 0..7)
//   orig = gate*256 + (s*32 + wn*8 + w)
__device__ __forceinline__ int orig_gate_col(int n) {
    int s = n >> 7, wn = (n >> 5) & 3, gate = (n >> 3) & 3, w = n & 7;
    return gate * 256 + s * 32 + wn * 8 + w;
}

// ---------------- prep kernels (rerun every replay; reset all state) ----
__global__ void prep_weights(const float* __restrict__ W_ih, const float* __restrict__ b_ih,
                             const float* __restrict__ W_hh, const float* __restrict__ b_hh,
                             const float* __restrict__ W_ho, const float* __restrict__ b_ho) {
    int n = blockIdx.x;         // 0..1023
    int k = threadIdx.x;        // 0..319
    int g = orig_gate_col(n);
    float w;
    if (k < Ddim) {
        w = W_ih[g * 64 + k];
    } else if (k < 64) {
        w = 0.0f;
    } else {
        int kh = k - 64;
        w = W_hh[g * Hdim + kh];
        #pragma unroll
        for (int j = 0; j < Odim; j++)
            w += W_ho[j * Hdim + kh] * W_ih[g * 64 + Ddim + j];
    }
    g_W[(size_t)n * KDIM + k] = __float2half_rn(w);
    if (k == 0) {
        float bb = b_ih[g] + b_hh[g];
        #pragma unroll
        for (int j = 0; j < Odim; j++)
            bb += b_ho[j] * W_ih[g * 64 + Ddim + j];
        g_bias[n] = bb;
    }
    if (n == 0 && k < MG) g_cnt[k * 32] = 0;   // reset sync counters each replay
}

__global__ void prep_x(const float* __restrict__ x) {
    size_t idx = (size_t)blockIdx.x * 256 + threadIdx.x;  // t*B*64 total
    int k = (int)(idx & 63);
    size_t r = idx >> 6;
    int b = (int)(r & (Bdim - 1));
    int t = (int)(r >> 9);
    float v = (k < Ddim) ? x[((size_t)b * Tdim + t) * Ddim + k] : 0.0f;
    g_xT[idx] = __float2half_rn(v);
}

__global__ void prep_state(const float* __restrict__ h0,
                           const float* __restrict__ W_ih,
                           const float* __restrict__ W_ho,
                           const float* __restrict__ b_ho) {
    int b = blockIdx.x;
    int tid = threadIdx.x;
    g_h16[0][b * Hdim + tid] = __float2half_rn(h0[b * Hdim + tid]);
    __shared__ float tmp[Odim];
    if (tid < Odim) {
        float a = b_ho[tid];
        for (int k = 0; k < Hdim; k++)
            a += h0[b * Hdim + k] * W_ho[tid * Hdim + k];
        tmp[tid] = a;
    }
    __syncthreads();
    for (int n = tid; n < G4H; n += 256) {
        int g = orig_gate_col(n);
        float a = 0.0f;
        #pragma unroll
        for (int j = 0; j < Odim; j++)
            a += tmp[j] * W_ih[g * 64 + Ddim + j];
        g_corr0[(size_t)b * G4H + n] = -a;
    }
}

// ---------------- SMEM layout (dynamic) ----------------
#define OFF_AS   0
#define OFF_WS   (OFF_AS + MT * AP * 2)          // 20992
#define OFF_WHO  (OFF_WS + NT * WP * 2)          // 104960
#define OFF_BHO  (OFF_WHO + Odim * Hdim * 4)     // 114176
#define SMEM_BYTES (OFF_BHO + 64)                // 114240

// out_{t_store} for this CTA's 4 designated rows (warps 0..3), fp16 h buffer p.
__device__ __forceinline__ void compute_out(int t_store, int p, int mBase, int s,
                                            const float* Who_s, const float* bho_s,
                                            float* __restrict__ out) {
    int wid = threadIdx.x >> 5, lane = threadIdx.x & 31;
    if (wid >= 4) return;
    int b = mBase + s * 4 + wid;
    const __half2* hp = (const __half2*)(g_h16[p] + (size_t)b * Hdim);
    float a[Odim];
    #pragma unroll
    for (int j = 0; j < Odim; j++) a[j] = 0.0f;
    #pragma unroll
    for (int c = 0; c < 4; c++) {
        __half2 hv2 = __ldcg(&hp[c * 32 + lane]);
        float lo = __low2float(hv2), hi = __high2float(hv2);
        int k = (c * 32 + lane) * 2;
        #pragma unroll
        for (int j = 0; j < Odim; j++) {
            a[j] = fmaf(lo, Who_s[j * Hdim + k], a[j]);
            a[j] = fmaf(hi, Who_s[j * Hdim + k + 1], a[j]);
        }
    }
    #pragma unroll
    for (int off = 16; off > 0; off >>= 1) {
        #pragma unroll
        for (int j = 0; j < Odim; j++)
            a[j] += __shfl_xor_sync(0xffffffffu, a[j], off);
    }
    if (lane < Odim)
        out[((size_t)b * Tdim + t_store) * Odim + lane] = a[lane] + bho_s[lane];
}

// one k-step: 3 ldmatrix + 4 mma
__device__ __forceinline__ void mma_kstep(int k0, float acc[4][4],
                                          uint32_t a_ptr, uint32_t b_ptr1, uint32_t b_ptr2) {
    uint32_t a0, a1, a2, a3, bb[8];
    asm volatile("ldmatrix.sync.aligned.m8n8.x4.shared.b16 {%0,%1,%2,%3}, [%4];"
                 : "=r"(a0), "=r"(a1), "=r"(a2), "=r"(a3)
                 : "r"(a_ptr + (uint32_t)(k0 * 2)));
    asm volatile("ldmatrix.sync.aligned.m8n8.x4.shared.b16 {%0,%1,%2,%3}, [%4];"
                 : "=r"(bb[0]), "=r"(bb[1]), "=r"(bb[2]), "=r"(bb[3])
                 : "r"(b_ptr1 + (uint32_t)(k0 * 2)));
    asm volatile("ldmatrix.sync.aligned.m8n8.x4.shared.b16 {%0,%1,%2,%3}, [%4];"
                 : "=r"(bb[4]), "=r"(bb[5]), "=r"(bb[6]), "=r"(bb[7])
                 : "r"(b_ptr2 + (uint32_t)(k0 * 2)));
    #pragma unroll
    for (int bn = 0; bn < 4; bn++) {
        asm volatile(
            "mma.sync.aligned.m16n8k16.row.col.f32.f16.f16.f32 "
            "{%0,%1,%2,%3}, {%4,%5,%6,%7}, {%8,%9}, {%0,%1,%2,%3};\n"
            : "+f"(acc[bn][0]), "+f"(acc[bn][1]),
              "+f"(acc[bn][2]), "+f"(acc[bn][3])
            : "r"(a0), "r"(a1), "r"(a2), "r"(a3),
              "r"(bb[bn * 2]), "r"(bb[bn * 2 + 1]));
    }
}

__global__ void __launch_bounds__(NTHREADS, 1)
rnn_kernel(const float* __restrict__ c0, const float* __restrict__ W_ho,
           const float* __restrict__ b_ho, float* __restrict__ out) {
    extern __shared__ char smem[];
    __half* As    = (__half*)(smem + OFF_AS);
    __half* Ws    = (__half*)(smem + OFF_WS);
    float*  Who_s = (float*)(smem + OFF_WHO);
    float*  bho_s = (float*)(smem + OFF_BHO);

    const int tid = threadIdx.x;
    const int m = blockIdx.x & (MG - 1);       // group
    const int s = blockIdx.x >> 4;             // slice 0..7
    const int mBase = m * MT;
    const int wid = tid >> 5, lane = tid & 31;
    const int wm = wid & 1, wn = wid >> 1;     // warp tile: rows wm*16, cols wn*32
    const int qg = lane >> 2;                  // row-in-tile
    const int w0 = (lane & 3) * 2;             // unit pair base within warp tile

    const uint32_t As_base = (uint32_t)__cvta_generic_to_shared(As);
    const uint32_t Ws_base = (uint32_t)__cvta_generic_to_shared(Ws);

    // ldmatrix lane addresses
    const uint32_t a_ptr = As_base +
        (uint32_t)(((wm * 16 + (lane & 15)) * AP + ((lane >> 4) << 3)) * 2);
    const uint32_t b_ptr1 = Ws_base +
        (uint32_t)(((wn * 32 + (lane & 7) + ((lane >> 4) << 3)) * WP + (((lane >> 3) & 1) << 3)) * 2);
    const uint32_t b_ptr2 = b_ptr1 + 16 * WP * 2;

    // per-thread fixed cell coordinates
    const int row0 = wm * 16 + qg;             // local rows row0, row0+8
    const int cb   = s * 32 + wn * 8 + w0;     // global unit base (2 units cb, cb+1)
    const int gb0  = mBase + row0;             // global batch rows
    const int gb1  = gb0 + 8;

    // ---- one-time loads ----
    for (int i = tid; i < NT * 40; i += NTHREADS) { // W slice: 128 rows x 40 x 16B
        int c = i / 40, ch = i % 40;
        *(uint4*)&Ws[c * WP + ch * 8] =
            *(const uint4*)&g_W[((size_t)(s * NT + c)) * KDIM + ch * 8];
    }
    for (int i = tid; i < Odim * Hdim; i += NTHREADS) Who_s[i] = W_ho[i];
    if (tid < Odim) bho_s[tid] = b_ho[tid];

    // registers: bias[gate][unitSel], c-state c_[j] (j: 0=r0u0 1=r0u1 2=r1u0 3=r1u1)
    float bi[4][2];
    #pragma unroll
    for (int g = 0; g < 4; g++) {
        bi[g][0] = g_bias[s * 128 + wn * 32 + g * 8 + w0];
        bi[g][1] = g_bias[s * 128 + wn * 32 + g * 8 + w0 + 1];
    }
    float c_[4];
    c_[0] = c0[(size_t)gb0 * Hdim + cb];
    c_[1] = c0[(size_t)gb0 * Hdim + cb + 1];
    c_[2] = c0[(size_t)gb1 * Hdim + cb];
    c_[3] = c0[(size_t)gb1 * Hdim + cb + 1];

    __syncthreads();

    int* cnt = &g_cnt[m * 32];

    // ---- time loop ----
    for (int t = 0; t < Tdim; t++) {
        const int p  = t & 1;        // h_{t-1} buffer
        const int p2 = p ^ 1;        // h_t buffer

        // x-part prefetch (independent of sync): 32 rows x 8 chunks, 1/thread  [group X]
        {
            const __half* xrow = g_xT + ((size_t)t * Bdim + mBase) * 64;
            int r = tid >> 3, ch = tid & 7;
            cp_async16(As_base + (uint32_t)((r * AP + ch * 8) * 2),
                       xrow + (size_t)r * 64 + ch * 8);
            asm volatile("cp.async.commit_group;\n" ::: "memory");
        }

        // warp-coalesced tight poll; each thread proceeds to issue its h loads
        if (t > 0) {
            int tgt = t * NSL;
            while (ld_acquire(cnt) < tgt) {}
        }

        // h-part load: 32 rows x 32 chunks, 4/thread  [group H]
        {
            const __half* hrow = g_h16[p] + (size_t)mBase * Hdim;
            #pragma unroll
            for (int it = 0; it < 4; it++) {
                int i = tid + it * NTHREADS;
                int r = i >> 5, ch = i & 31;
                cp_async16(As_base + (uint32_t)((r * AP + 64 + ch * 8) * 2),
                           hrow + (size_t)r * Hdim + ch * 8);
            }
            asm volatile("cp.async.commit_group;\n" ::: "memory");
        }

        // out_{t-1}: buffer p is stable until group advances past step t
        if (t > 0) compute_out(t - 1, p, mBase, s, Who_s, bho_s, out);

        float acc[4][4];
        #pragma unroll
        for (int b0 = 0; b0 < 4; b0++)
            #pragma unroll
            for (int c0i = 0; c0i < 4; c0i++) acc[b0][c0i] = 0.0f;

        // x-part MMA overlapped with h-load latency
        asm volatile("cp.async.wait_group 1;\n" ::: "memory");
        __syncthreads();
        #pragma unroll
        for (int k0 = 0; k0 < 64; k0 += 16)
            mma_kstep(k0, acc, a_ptr, b_ptr1, b_ptr2);

        asm volatile("cp.async.wait_group 0;\n" ::: "memory");
        __syncthreads();
        #pragma unroll 4
        for (int k0 = 64; k0 < KDIM; k0 += 16)
            mma_kstep(k0, acc, a_ptr, b_ptr1, b_ptr2);

        // ---- register epilogue: acc[gate][j], j = (rowSel<<1)|unitSel ----
        if (t == 0) {
            #pragma unroll
            for (int g = 0; g < 4; g++) {
                int nIdx = s * 128 + wn * 32 + g * 8 + w0;
                acc[g][0] += g_corr0[(size_t)gb0 * G4H + nIdx];
                acc[g][1] += g_corr0[(size_t)gb0 * G4H + nIdx + 1];
                acc[g][2] += g_corr0[(size_t)gb1 * G4H + nIdx];
                acc[g][3] += g_corr0[(size_t)gb1 * G4H + nIdx + 1];
            }
        }
        float hv[4];
        #pragma unroll
        for (int j = 0; j < 4; j++) {
            int us = j & 1;
            float iS = sigf(acc[0][j] + bi[0][us]);
            float fS = sigf(acc[1][j] + bi[1][us]);
            float gT = tanha(acc[2][j] + bi[2][us]);
            float oS = sigf(acc[3][j] + bi[3][us]);
            c_[j] = fmaf(fS, c_[j], iS * gT);
            hv[j] = oS * tanha(c_[j]);
        }
        *(__half2*)&g_h16[p2][(size_t)gb0 * Hdim + cb] = __floats2half2_rn(hv[0], hv[1]);
        *(__half2*)&g_h16[p2][(size_t)gb1 * Hdim + cb] = __floats2half2_rn(hv[2], hv[3]);

        __syncthreads();
        if (tid == 0) red_release_add(cnt, 1);
    }

    // final output out_{T-1} (h_{T-1} lives in buffer 0 for even Tdim)
    {
        int tgt = Tdim * NSL;
        while (ld_acquire(cnt) < tgt) {}
    }
    compute_out(Tdim - 1, 0, mBase, s, Who_s, bho_s, out);
}

// ---------------- launch ----------------
extern "C" void kernel_launch(void* const* d_in, const int* in_sizes, int n_in,
                              void* d_out, int out_size) {
    const float* x    = (const float*)d_in[0];
    // d_in[1] = lengths (unused by the reference)
    const float* h0   = (const float*)d_in[2];
    const float* c0   = (const float*)d_in[3];
    const float* W_ih = (const float*)d_in[4];
    const float* b_ih = (const float*)d_in[5];
    const float* W_hh = (const float*)d_in[6];
    const float* b_hh = (const float*)d_in[7];
    const float* W_ho = (const float*)d_in[8];
    const float* b_ho = (const float*)d_in[9];
    float* out = (float*)d_out;

    cudaFuncSetAttribute(rnn_kernel, cudaFuncAttributeMaxDynamicSharedMemorySize, SMEM_BYTES);

    prep_weights<<<G4H, KDIM>>>(W_ih, b_ih, W_hh, b_hh, W_ho, b_ho);
    prep_x<<<(Tdim * Bdim * 64) / 256, 256>>>(x);
    prep_state<<<Bdim, 256>>>(h0, W_ih, W_ho, b_ho);
    rnn_kernel<<<NCTA, NTHREADS, SMEM_BYTES>>>(c0, W_ho, b_ho, out);
}